// round 16
// baseline (speedup 1.0000x reference)
#include <cuda_runtime.h>
#include <cuda_fp16.h>
#include <cstdint>

// (B, N, H, D) = (2, 4096, 8, 64)
#define BATCH 2
#define SEQ   4096
#define NH    8
#define HD    64
#define MODEL 512
#define BM    128            // query rows per CTA (4 warps x 32)
#define BN    64             // keys per tile
#define NTILES (SEQ / BN)    // 64
#define LS 0.180336879f      // 0.125 * log2(e)

// Device scratch (no cudaMalloc allowed)
__device__ __align__(16) float  g_attn[(size_t)BATCH * SEQ * MODEL];
__device__ __align__(16) __half g_qh[(size_t)BATCH * NH * SEQ * HD];
__device__ __align__(16) __half g_kh[(size_t)BATCH * NH * SEQ * HD];
__device__ __align__(16) __half g_vh[(size_t)BATCH * NH * SEQ * HD];

// SMEM layout (bytes). Row pitch = 144 B. Triple-buffered K/V.
#define RPITCH 144
#define TBUF   9216                  // 64 * 144
#define QS_B 0                       // 128 * 144 = 18432
#define KS_B 18432                   // 3 x 9216
#define VS_B (KS_B + 3 * TBUF)       // 46080
#define SMEM_BYTES (VS_B + 3 * TBUF) // 73728 (x2 CTAs = 144 KB/SM)

__device__ __forceinline__ uint32_t smem_u32(const void* p) {
    uint32_t a;
    asm("{ .reg .u64 t; cvta.to.shared.u64 t, %1; cvt.u32.u64 %0, t; }"
        : "=r"(a) : "l"(p));
    return a;
}
__device__ __forceinline__ float ex2(float x) {
    float r; asm("ex2.approx.ftz.f32 %0, %1;" : "=f"(r) : "f"(x)); return r;
}
__device__ __forceinline__ uint32_t ex2_h2(uint32_t x) {
    uint32_t r; asm("ex2.approx.f16x2 %0, %1;" : "=r"(r) : "r"(x)); return r;
}
__device__ __forceinline__ void cp_async16(uint32_t dst, const void* src) {
    asm volatile("cp.async.cg.shared.global [%0], [%1], 16;"
                 :: "r"(dst), "l"(src) : "memory");
}
#define CP_COMMIT() asm volatile("cp.async.commit_group;" ::: "memory")
#define CP_WAIT(n)  asm volatile("cp.async.wait_group %0;" :: "n"(n) : "memory")

__device__ __forceinline__ void ldsm_x4(uint32_t& r0, uint32_t& r1,
                                        uint32_t& r2, uint32_t& r3, uint32_t a) {
    asm volatile("ldmatrix.sync.aligned.m8n8.x4.shared.b16 {%0,%1,%2,%3}, [%4];"
                 : "=r"(r0), "=r"(r1), "=r"(r2), "=r"(r3) : "r"(a));
}
__device__ __forceinline__ void ldsm_x4_t(uint32_t& r0, uint32_t& r1,
                                          uint32_t& r2, uint32_t& r3, uint32_t a) {
    asm volatile("ldmatrix.sync.aligned.m8n8.x4.trans.shared.b16 {%0,%1,%2,%3}, [%4];"
                 : "=r"(r0), "=r"(r1), "=r"(r2), "=r"(r3) : "r"(a));
}
__device__ __forceinline__ void mma_f16(float c[4], const uint32_t a[4],
                                        uint32_t b0, uint32_t b1) {
    asm volatile(
        "mma.sync.aligned.m16n8k16.row.col.f32.f16.f16.f32 "
        "{%0,%1,%2,%3}, {%4,%5,%6,%7}, {%8,%9}, {%0,%1,%2,%3};"
        : "+f"(c[0]), "+f"(c[1]), "+f"(c[2]), "+f"(c[3])
        : "r"(a[0]), "r"(a[1]), "r"(a[2]), "r"(a[3]), "r"(b0), "r"(b1));
}
__device__ __forceinline__ uint32_t h2pack(float a, float b) {
    __half2 h = __floats2half2_rn(a, b);
    return *reinterpret_cast<uint32_t*>(&h);
}

// ---------------------------------------------------------------------------
__global__ void noop_kernel() {}

// ---------------------------------------------------------------------------
// Prolog: fp32 [b,n,h*d] -> fp16 [b,h,n,d] for q,k,v
// ---------------------------------------------------------------------------
__global__ __launch_bounds__(256)
void cvt_kernel(const float* __restrict__ q, const float* __restrict__ k,
                const float* __restrict__ v)
{
    int c = blockIdx.x * 256 + threadIdx.x;
    int which = blockIdx.y;
    const float* src = (which == 0) ? q : (which == 1) ? k : v;
    __half* dst = (which == 0) ? g_qh : (which == 1) ? g_kh : g_vh;

    int bh  = c >> 15;
    int rem = c & 32767;
    int n   = rem >> 3;
    int j   = rem & 7;
    int b = bh >> 3, h = bh & 7;

    const float4* in = (const float4*)(src + ((size_t)(b * SEQ + n)) * MODEL + h * HD + j * 8);
    float4 x = in[0], y = in[1];
    uint4 o;
    o.x = h2pack(x.x, x.y); o.y = h2pack(x.z, x.w);
    o.z = h2pack(y.x, y.y); o.w = h2pack(y.z, y.w);
    *(uint4*)(dst + (size_t)c * 8) = o;
}

// ---------------------------------------------------------------------------
// fp16 mma.sync flash attention. BN=64 tiles, triple buffer, one barrier per
// tile, per-m softmax->MMA2. Row-sums moved OFF the tensor pipe (fp32 unpack
// of the packed P fragments, per-lane quad-partials, epilogue shfl-reduce):
// removes 8 of 136 mma/warp/tile to test/exploit the mma.sync rate ceiling.
// grid=(B*NH, SEQ/BM), block=128 (4 warps), 2 CTAs/SM.
// ---------------------------------------------------------------------------
__global__ __launch_bounds__(128, 2)
void attn_tc_kernel()
{
    extern __shared__ char smc[];
    const uint32_t sb = smem_u32(smc);

    const int tid  = threadIdx.x;
    const int lane = tid & 31;
    const int wid  = tid >> 5;
    const int g    = lane >> 2;
    const int t    = lane & 3;
    const int wq0  = wid * 32;

    const int bh = blockIdx.x;
    const int b  = bh >> 3;
    const int h  = bh & 7;
    const int q0 = blockIdx.y * BM;

    const __half* qh = g_qh + (size_t)bh * SEQ * HD;
    const __half* kh = g_kh + (size_t)bh * SEQ * HD;
    const __half* vh = g_vh + (size_t)bh * SEQ * HD;

    // ---- Stage this warp's 32 Q rows, pull fragments into registers ----
#pragma unroll
    for (int it = 0; it < 8; it++) {
        int c = wq0 * 8 + it * 32 + lane;
        int row = c >> 3, c16 = c & 7;
        *(uint4*)(smc + QS_B + row * RPITCH + c16 * 16) =
            *(const uint4*)(qh + (size_t)(q0 + row) * HD + c16 * 8);
    }
    __syncwarp();

    uint32_t qa[2][4][4];
#pragma unroll
    for (int m = 0; m < 2; m++)
#pragma unroll
        for (int s = 0; s < 4; s++) {
            uint32_t addr = sb + QS_B + (wq0 + 16 * m + (lane & 15)) * RPITCH
                          + ((lane >> 4) * 16) + s * 32;
            ldsm_x4(qa[m][s][0], qa[m][s][1], qa[m][s][2], qa[m][s][3], addr);
        }

    const uint32_t koff = ((lane & 7) + ((lane >> 4) << 3)) * RPITCH
                        + ((lane >> 3) & 1) * 16;
    const uint32_t voff = ((lane & 7) + (((lane >> 3) & 1) << 3)) * RPITCH
                        + ((lane >> 4) & 1) * 16;

    // ---- Online-softmax state (l as per-lane quad-partials, fp32) ----
    float mrow[2][2] = {{-1e30f, -1e30f}, {-1e30f, -1e30f}};
    float lrow[2][2] = {{0.f, 0.f}, {0.f, 0.f}};
    float Oacc[2][8][4];
#pragma unroll
    for (int m = 0; m < 2; m++)
#pragma unroll
        for (int n = 0; n < 8; n++)
#pragma unroll
            for (int i = 0; i < 4; i++) Oacc[m][n][i] = 0.f;

    // ---- Preload tiles 0 and 1 ----
#pragma unroll
    for (int pt = 0; pt < 2; pt++) {
        const uint32_t kb = sb + KS_B + pt * TBUF;
        const uint32_t vb = sb + VS_B + pt * TBUF;
        const int j0 = pt * BN;
#pragma unroll
        for (int r = 0; r < 4; r++) {
            int c = r * 128 + tid;
            int row = c >> 3, c16 = c & 7;
            cp_async16(kb + row * RPITCH + c16 * 16,
                       kh + (size_t)(j0 + row) * HD + c16 * 8);
            cp_async16(vb + row * RPITCH + c16 * 16,
                       vh + (size_t)(j0 + row) * HD + c16 * 8);
        }
        CP_COMMIT();
    }

    for (int kt = 0; kt < NTILES; kt++) {
        const int cur = kt % 3;

        if (kt + 1 < NTILES) { CP_WAIT(1); } else { CP_WAIT(0); }
        __syncthreads();

        if (kt + 2 < NTILES) {
            const int j0 = (kt + 2) * BN;
            const int nb = (kt + 2) % 3;
            const uint32_t kb = sb + KS_B + nb * TBUF;
            const uint32_t vb = sb + VS_B + nb * TBUF;
#pragma unroll
            for (int r = 0; r < 4; r++) {
                int c = r * 128 + tid;
                int row = c >> 3, c16 = c & 7;
                cp_async16(kb + row * RPITCH + c16 * 16,
                           kh + (size_t)(j0 + row) * HD + c16 * 8);
                cp_async16(vb + row * RPITCH + c16 * 16,
                           vh + (size_t)(j0 + row) * HD + c16 * 8);
            }
            CP_COMMIT();
        }

        // ---- MMA1: S = Q . K^T (both m-tiles; shared K frags) ----
        float S[2][8][4];
#pragma unroll
        for (int m = 0; m < 2; m++)
#pragma unroll
            for (int n = 0; n < 8; n++)
#pragma unroll
                for (int i = 0; i < 4; i++) S[m][n][i] = 0.f;

        const uint32_t kbase = sb + KS_B + cur * TBUF + koff;
#pragma unroll
        for (int s = 0; s < 4; s++) {
#pragma unroll
            for (int np = 0; np < 4; np++) {
                uint32_t b0, b1, b2, b3;
                ldsm_x4(b0, b1, b2, b3, kbase + np * (16 * RPITCH) + s * 32);
                mma_f16(S[0][2 * np],     qa[0][s], b0, b1);
                mma_f16(S[0][2 * np + 1], qa[0][s], b2, b3);
                mma_f16(S[1][2 * np],     qa[1][s], b0, b1);
                mma_f16(S[1][2 * np + 1], qa[1][s], b2, b3);
            }
        }

        // ---- Per-m: softmax(m) -> row sums (FMA pipe) -> MMA2(m) ----
        const uint32_t vbase = sb + VS_B + cur * TBUF + voff;
#pragma unroll
        for (int m = 0; m < 2; m++) {
            float mtA = -1e30f, mtB = -1e30f;
#pragma unroll
            for (int n = 0; n < 8; n++) {
                mtA = fmaxf(mtA, fmaxf(S[m][n][0], S[m][n][1]));
                mtB = fmaxf(mtB, fmaxf(S[m][n][2], S[m][n][3]));
            }
            mtA = fmaxf(mtA, __shfl_xor_sync(0xFFFFFFFFu, mtA, 1));
            mtA = fmaxf(mtA, __shfl_xor_sync(0xFFFFFFFFu, mtA, 2));
            mtB = fmaxf(mtB, __shfl_xor_sync(0xFFFFFFFFu, mtB, 1));
            mtB = fmaxf(mtB, __shfl_xor_sync(0xFFFFFFFFu, mtB, 2));

            float mnA = fmaxf(mrow[m][0], mtA);
            float mnB = fmaxf(mrow[m][1], mtB);
            float corrA = ex2((mrow[m][0] - mnA) * LS);
            float corrB = ex2((mrow[m][1] - mnB) * LS);
            mrow[m][0] = mnA; mrow[m][1] = mnB;
            const float bA = mnA * LS, bB = mnB * LS;

            uint32_t pa[4][4];
#pragma unroll
            for (int s = 0; s < 4; s++) {
                pa[s][0] = ex2_h2(h2pack(fmaf(S[m][2*s][0],   LS, -bA),
                                         fmaf(S[m][2*s][1],   LS, -bA)));
                pa[s][1] = ex2_h2(h2pack(fmaf(S[m][2*s][2],   LS, -bB),
                                         fmaf(S[m][2*s][3],   LS, -bB)));
                pa[s][2] = ex2_h2(h2pack(fmaf(S[m][2*s+1][0], LS, -bA),
                                         fmaf(S[m][2*s+1][1], LS, -bA)));
                pa[s][3] = ex2_h2(h2pack(fmaf(S[m][2*s+1][2], LS, -bB),
                                         fmaf(S[m][2*s+1][3], LS, -bB)));
            }

            // Row sums in fp32 on the FMA pipe (replaces the ones-MMA:
            // -8 tensor instructions per warp per tile).
            {
                float sA = 0.f, sB = 0.f;
#pragma unroll
                for (int s = 0; s < 4; s++) {
                    float2 a0 = __half22float2(*(__half2*)&pa[s][0]);
                    float2 a2 = __half22float2(*(__half2*)&pa[s][2]);
                    float2 b1 = __half22float2(*(__half2*)&pa[s][1]);
                    float2 b3 = __half22float2(*(__half2*)&pa[s][3]);
                    sA += (a0.x + a0.y) + (a2.x + a2.y);
                    sB += (b1.x + b1.y) + (b3.x + b3.y);
                }
                lrow[m][0] = lrow[m][0] * corrA + sA;
                lrow[m][1] = lrow[m][1] * corrB + sB;
            }

            // Rescale O accumulators of this m-tile
#pragma unroll
            for (int n = 0; n < 8; n++) {
                Oacc[m][n][0] *= corrA; Oacc[m][n][1] *= corrA;
                Oacc[m][n][2] *= corrB; Oacc[m][n][3] *= corrB;
            }

            // MMA2(m): O += P . V
#pragma unroll
            for (int s = 0; s < 4; s++) {
#pragma unroll
                for (int nd = 0; nd < 4; nd++) {
                    uint32_t b0, b1, b2, b3;
                    ldsm_x4_t(b0, b1, b2, b3,
                              vbase + s * (16 * RPITCH) + nd * 32);
                    mma_f16(Oacc[m][2 * nd],     pa[s], b0, b1);
                    mma_f16(Oacc[m][2 * nd + 1], pa[s], b2, b3);
                }
            }
        }
    }

    // ---- Final l reduction across quad, normalize, write to g_attn ----
#pragma unroll
    for (int m = 0; m < 2; m++) {
        float lA = lrow[m][0], lB = lrow[m][1];
        lA += __shfl_xor_sync(0xFFFFFFFFu, lA, 1);
        lA += __shfl_xor_sync(0xFFFFFFFFu, lA, 2);
        lB += __shfl_xor_sync(0xFFFFFFFFu, lB, 1);
        lB += __shfl_xor_sync(0xFFFFFFFFu, lB, 2);
        float invA = 1.f / lA;
        float invB = 1.f / lB;
        int rA = q0 + wq0 + 16 * m + g;
        int rB = rA + 8;
        float* opA = g_attn + ((size_t)(b * SEQ + rA)) * MODEL + h * HD;
        float* opB = g_attn + ((size_t)(b * SEQ + rB)) * MODEL + h * HD;
#pragma unroll
        for (int n = 0; n < 8; n++) {
            *(float2*)(opA + n * 8 + 2 * t) =
                make_float2(Oacc[m][n][0] * invA, Oacc[m][n][1] * invA);
            *(float2*)(opB + n * 8 + 2 * t) =
                make_float2(Oacc[m][n][2] * invB, Oacc[m][n][3] * invB);
        }
    }
}

// ---------------------------------------------------------------------------
// Output projection: out[8192,64] = g_attn[8192,512] @ W[512,64] + b[64]
// ---------------------------------------------------------------------------
#define GBM 32
#define GBK 64
#define APAD 68
__global__ __launch_bounds__(256)
void proj_kernel(const float* __restrict__ W,
                 const float* __restrict__ bias,
                 float* __restrict__ out)
{
    __shared__ float As[GBM][APAD];
    __shared__ float Ws[GBK][64];

    const int row0 = blockIdx.x * GBM;
    const int tid  = threadIdx.x;
    const int tr   = tid >> 4;
    const int tc   = tid & 15;

    float acc[2][4];
#pragma unroll
    for (int i = 0; i < 2; i++)
#pragma unroll
        for (int j = 0; j < 4; j++) acc[i][j] = 0.f;

    for (int k0 = 0; k0 < MODEL; k0 += GBK) {
#pragma unroll
        for (int it = 0; it < 2; it++) {
            int idx = it * 256 + tid;
            int r = idx >> 4, c4 = idx & 15;
            *(float4*)&As[r][c4 * 4] =
                *(const float4*)(g_attn + ((size_t)(row0 + r)) * MODEL + k0 + c4 * 4);
        }
#pragma unroll
        for (int it = 0; it < 4; it++) {
            int idx = it * 256 + tid;
            int r = idx >> 4, c4 = idx & 15;
            *(float4*)&Ws[r][c4 * 4] =
                *(const float4*)(W + ((size_t)(k0 + r)) * 64 + c4 * 4);
        }
        __syncthreads();

#pragma unroll
        for (int kk = 0; kk < GBK; kk++) {
            float4 w4 = *(const float4*)&Ws[kk][tc * 4];
#pragma unroll
            for (int i = 0; i < 2; i++) {
                float a = As[tr * 2 + i][kk];
                acc[i][0] += a * w4.x;
                acc[i][1] += a * w4.y;
                acc[i][2] += a * w4.z;
                acc[i][3] += a * w4.w;
            }
        }
        __syncthreads();
    }

#pragma unroll
    for (int i = 0; i < 2; i++) {
        int r = row0 + tr * 2 + i;
        float4 o;
        o.x = acc[i][0] + bias[tc * 4 + 0];
        o.y = acc[i][1] + bias[tc * 4 + 1];
        o.z = acc[i][2] + bias[tc * 4 + 2];
        o.w = acc[i][3] + bias[tc * 4 + 3];
        *(float4*)(out + (size_t)r * 64 + tc * 4) = o;
    }
}

// ---------------------------------------------------------------------------
extern "C" void kernel_launch(void* const* d_in, const int* in_sizes, int n_in,
                              void* d_out, int out_size)
{
    const float* q    = (const float*)d_in[0];
    const float* k    = (const float*)d_in[1];
    const float* v    = (const float*)d_in[2];
    const float* Wout = (const float*)d_in[3];
    const float* bout = (const float*)d_in[4];
    float* out = (float*)d_out;

    static bool attr_set = false;
    if (!attr_set) {
        cudaFuncSetAttribute(attn_tc_kernel,
                             cudaFuncAttributeMaxDynamicSharedMemorySize, SMEM_BYTES);
        attr_set = true;
    }

    cvt_kernel<<<dim3(2048, 3), 256>>>(q, k, v);

    // Spacers keep attn_tc_kernel in the ncu capture slot (verification of
    // the tensor-duration prediction).
    noop_kernel<<<1, 1>>>();
    noop_kernel<<<1, 1>>>();

    dim3 agrid(BATCH * NH, SEQ / BM);
    attn_tc_kernel<<<agrid, BM, SMEM_BYTES>>>();

    dim3 pgrid((BATCH * SEQ) / GBM);
    proj_kernel<<<pgrid, 256>>>(Wout, bout, out);
}

// round 17
// speedup vs baseline: 1.0902x; 1.0902x over previous
#include <cuda_runtime.h>
#include <cuda_fp16.h>
#include <cstdint>

// (B, N, H, D) = (2, 4096, 8, 64)
#define BATCH 2
#define SEQ   4096
#define NH    8
#define HD    64
#define MODEL 512
#define BM    128            // query rows per CTA (4 warps x 32)
#define BN    64             // keys per tile
#define NTILES (SEQ / BN)    // 64
#define LS 0.180336879f      // 0.125 * log2(e)
#define ONES2 0x3C003C00u    // half2(1.0, 1.0)

// Device scratch (no cudaMalloc allowed)
__device__ __align__(16) __half g_attnh[(size_t)BATCH * SEQ * MODEL];
__device__ __align__(16) __half g_kh[(size_t)BATCH * NH * SEQ * HD];
__device__ __align__(16) __half g_vh[(size_t)BATCH * NH * SEQ * HD];
__device__ __align__(16) __half g_wh[(size_t)MODEL * HD];

// SMEM layout (bytes). Row pitch = 144 B. Triple-buffered K/V.
#define RPITCH 144
#define TBUF   9216                  // 64 * 144
#define QS_B 0                       // 128 * 144 = 18432
#define KS_B 18432                   // 3 x 9216
#define VS_B (KS_B + 3 * TBUF)       // 46080
#define SMEM_BYTES (VS_B + 3 * TBUF) // 73728 (x2 CTAs = 144 KB/SM)

__device__ __forceinline__ uint32_t smem_u32(const void* p) {
    uint32_t a;
    asm("{ .reg .u64 t; cvta.to.shared.u64 t, %1; cvt.u32.u64 %0, t; }"
        : "=r"(a) : "l"(p));
    return a;
}
__device__ __forceinline__ float ex2(float x) {
    float r; asm("ex2.approx.ftz.f32 %0, %1;" : "=f"(r) : "f"(x)); return r;
}
__device__ __forceinline__ uint32_t ex2_h2(uint32_t x) {
    uint32_t r; asm("ex2.approx.f16x2 %0, %1;" : "=r"(r) : "r"(x)); return r;
}
__device__ __forceinline__ void cp_async16(uint32_t dst, const void* src) {
    asm volatile("cp.async.cg.shared.global [%0], [%1], 16;"
                 :: "r"(dst), "l"(src) : "memory");
}
#define CP_COMMIT() asm volatile("cp.async.commit_group;" ::: "memory")
#define CP_WAIT(n)  asm volatile("cp.async.wait_group %0;" :: "n"(n) : "memory")

__device__ __forceinline__ void ldsm_x4(uint32_t& r0, uint32_t& r1,
                                        uint32_t& r2, uint32_t& r3, uint32_t a) {
    asm volatile("ldmatrix.sync.aligned.m8n8.x4.shared.b16 {%0,%1,%2,%3}, [%4];"
                 : "=r"(r0), "=r"(r1), "=r"(r2), "=r"(r3) : "r"(a));
}
__device__ __forceinline__ void ldsm_x4_t(uint32_t& r0, uint32_t& r1,
                                          uint32_t& r2, uint32_t& r3, uint32_t a) {
    asm volatile("ldmatrix.sync.aligned.m8n8.x4.trans.shared.b16 {%0,%1,%2,%3}, [%4];"
                 : "=r"(r0), "=r"(r1), "=r"(r2), "=r"(r3) : "r"(a));
}
__device__ __forceinline__ void mma_f16(float c[4], const uint32_t a[4],
                                        uint32_t b0, uint32_t b1) {
    asm volatile(
        "mma.sync.aligned.m16n8k16.row.col.f32.f16.f16.f32 "
        "{%0,%1,%2,%3}, {%4,%5,%6,%7}, {%8,%9}, {%0,%1,%2,%3};"
        : "+f"(c[0]), "+f"(c[1]), "+f"(c[2]), "+f"(c[3])
        : "r"(a[0]), "r"(a[1]), "r"(a[2]), "r"(a[3]), "r"(b0), "r"(b1));
}
__device__ __forceinline__ uint32_t h2pack(float a, float b) {
    __half2 h = __floats2half2_rn(a, b);
    return *reinterpret_cast<uint32_t*>(&h);
}

// ---------------------------------------------------------------------------
__global__ void noop_kernel() {}

// ---------------------------------------------------------------------------
// Prolog: fp32 [b,n,h*d] -> fp16 [b,h,n,d] for K and V only (Q converted
// inline by the attention kernel — it is read exactly once).
// ---------------------------------------------------------------------------
__global__ __launch_bounds__(256)
void cvt_kernel(const float* __restrict__ k, const float* __restrict__ v)
{
    int c = blockIdx.x * 256 + threadIdx.x;
    int which = blockIdx.y;
    const float* src = (which == 0) ? k : v;
    __half* dst = (which == 0) ? g_kh : g_vh;

    int bh  = c >> 15;
    int rem = c & 32767;
    int n   = rem >> 3;
    int j   = rem & 7;
    int b = bh >> 3, h = bh & 7;

    const float4* in = (const float4*)(src + ((size_t)(b * SEQ + n)) * MODEL + h * HD + j * 8);
    float4 x = in[0], y = in[1];
    uint4 o;
    o.x = h2pack(x.x, x.y); o.y = h2pack(x.z, x.w);
    o.z = h2pack(y.x, y.y); o.w = h2pack(y.z, y.w);
    *(uint4*)(dst + (size_t)c * 8) = o;
}

// W fp32 [512,64] -> fp16 (contiguous). 32768 elements = 4096 8-half chunks.
__global__ __launch_bounds__(256)
void wcvt_kernel(const float* __restrict__ W)
{
    int c = blockIdx.x * 256 + threadIdx.x;   // 0..4095
    const float4* in = (const float4*)(W + (size_t)c * 8);
    float4 x = in[0], y = in[1];
    uint4 o;
    o.x = h2pack(x.x, x.y); o.y = h2pack(x.z, x.w);
    o.z = h2pack(y.x, y.y); o.w = h2pack(y.z, y.w);
    *(uint4*)(g_wh + (size_t)c * 8) = o;
}

// ---------------------------------------------------------------------------
// fp16 mma.sync flash attention (R14 config — measured best, 211.5us):
// triple-buffered K/V, one barrier/tile, per-m MMA1 ping-pong -> softmax ->
// ones-MMA L -> MMA2 ping-pong. Q converted fp32->fp16 inline at staging.
// Output stored as fp16 to g_attnh.
// grid=(B*NH, SEQ/BM), block=128 (4 warps), 2 CTAs/SM.
// ---------------------------------------------------------------------------
__global__ __launch_bounds__(128, 2)
void attn_tc_kernel(const float* __restrict__ qf)
{
    extern __shared__ char smc[];
    const uint32_t sb = smem_u32(smc);

    const int tid  = threadIdx.x;
    const int lane = tid & 31;
    const int wid  = tid >> 5;
    const int g    = lane >> 2;
    const int t    = lane & 3;
    const int wq0  = wid * 32;

    const int bh = blockIdx.x;
    const int b  = bh >> 3;
    const int h  = bh & 7;
    const int q0 = blockIdx.y * BM;

    const __half* kh = g_kh + (size_t)bh * SEQ * HD;
    const __half* vh = g_vh + (size_t)bh * SEQ * HD;

    // ---- Stage this warp's 32 Q rows (fp32 -> fp16 inline) ----
#pragma unroll
    for (int it = 0; it < 8; it++) {
        int c = wq0 * 8 + it * 32 + lane;
        int row = c >> 3, c16 = c & 7;
        const float4* in = (const float4*)(qf
            + ((size_t)(b * SEQ + q0 + row)) * MODEL + h * HD + c16 * 8);
        float4 x = in[0], y = in[1];
        uint4 o;
        o.x = h2pack(x.x, x.y); o.y = h2pack(x.z, x.w);
        o.z = h2pack(y.x, y.y); o.w = h2pack(y.z, y.w);
        *(uint4*)(smc + QS_B + row * RPITCH + c16 * 16) = o;
    }
    __syncwarp();

    uint32_t qa[2][4][4];
#pragma unroll
    for (int m = 0; m < 2; m++)
#pragma unroll
        for (int s = 0; s < 4; s++) {
            uint32_t addr = sb + QS_B + (wq0 + 16 * m + (lane & 15)) * RPITCH
                          + ((lane >> 4) * 16) + s * 32;
            ldsm_x4(qa[m][s][0], qa[m][s][1], qa[m][s][2], qa[m][s][3], addr);
        }

    const uint32_t koff = ((lane & 7) + ((lane >> 4) << 3)) * RPITCH
                        + ((lane >> 3) & 1) * 16;
    const uint32_t voff = ((lane & 7) + (((lane >> 3) & 1) << 3)) * RPITCH
                        + ((lane >> 4) & 1) * 16;

    // ---- Online-softmax state ----
    float mrow[2][2] = {{-1e30f, -1e30f}, {-1e30f, -1e30f}};
    float Lacc[2][4];
    float Oacc[2][8][4];
#pragma unroll
    for (int m = 0; m < 2; m++) {
#pragma unroll
        for (int i = 0; i < 4; i++) Lacc[m][i] = 0.f;
#pragma unroll
        for (int n = 0; n < 8; n++)
#pragma unroll
            for (int i = 0; i < 4; i++) Oacc[m][n][i] = 0.f;
    }

    // ---- Preload tiles 0 and 1 ----
#pragma unroll
    for (int pt = 0; pt < 2; pt++) {
        const uint32_t kb = sb + KS_B + pt * TBUF;
        const uint32_t vb = sb + VS_B + pt * TBUF;
        const int j0 = pt * BN;
#pragma unroll
        for (int r = 0; r < 4; r++) {
            int c = r * 128 + tid;
            int row = c >> 3, c16 = c & 7;
            cp_async16(kb + row * RPITCH + c16 * 16,
                       kh + (size_t)(j0 + row) * HD + c16 * 8);
            cp_async16(vb + row * RPITCH + c16 * 16,
                       vh + (size_t)(j0 + row) * HD + c16 * 8);
        }
        CP_COMMIT();
    }

    for (int kt = 0; kt < NTILES; kt++) {
        const int cur = kt % 3;

        if (kt + 1 < NTILES) { CP_WAIT(1); } else { CP_WAIT(0); }
        __syncthreads();

        if (kt + 2 < NTILES) {
            const int j0 = (kt + 2) * BN;
            const int nb = (kt + 2) % 3;
            const uint32_t kb = sb + KS_B + nb * TBUF;
            const uint32_t vb = sb + VS_B + nb * TBUF;
#pragma unroll
            for (int r = 0; r < 4; r++) {
                int c = r * 128 + tid;
                int row = c >> 3, c16 = c & 7;
                cp_async16(kb + row * RPITCH + c16 * 16,
                           kh + (size_t)(j0 + row) * HD + c16 * 8);
                cp_async16(vb + row * RPITCH + c16 * 16,
                           vh + (size_t)(j0 + row) * HD + c16 * 8);
            }
            CP_COMMIT();
        }

        const uint32_t kbase = sb + KS_B + cur * TBUF + koff;
        const uint32_t vbase = sb + VS_B + cur * TBUF + voff;

        // ---- Per-m: MMA1(m) -> softmax(m) -> L(m) -> MMA2(m) ----
#pragma unroll
        for (int m = 0; m < 2; m++) {
            float S[8][4];
#pragma unroll
            for (int n = 0; n < 8; n++)
#pragma unroll
                for (int i = 0; i < 4; i++) S[n][i] = 0.f;

            uint32_t bb[2][4];
            ldsm_x4(bb[0][0], bb[0][1], bb[0][2], bb[0][3], kbase);
#pragma unroll
            for (int i = 0; i < 16; i++) {
                const int c2 = i & 1;
                if (i < 15) {
                    const int ni = i + 1;
                    ldsm_x4(bb[c2 ^ 1][0], bb[c2 ^ 1][1],
                            bb[c2 ^ 1][2], bb[c2 ^ 1][3],
                            kbase + (ni & 3) * (16 * RPITCH) + (ni >> 2) * 32);
                }
                const int s = i >> 2, np = i & 3;
                mma_f16(S[2 * np],     qa[m][s], bb[c2][0], bb[c2][1]);
                mma_f16(S[2 * np + 1], qa[m][s], bb[c2][2], bb[c2][3]);
            }

            float mtA = -1e30f, mtB = -1e30f;
#pragma unroll
            for (int n = 0; n < 8; n++) {
                mtA = fmaxf(mtA, fmaxf(S[n][0], S[n][1]));
                mtB = fmaxf(mtB, fmaxf(S[n][2], S[n][3]));
            }
            mtA = fmaxf(mtA, __shfl_xor_sync(0xFFFFFFFFu, mtA, 1));
            mtA = fmaxf(mtA, __shfl_xor_sync(0xFFFFFFFFu, mtA, 2));
            mtB = fmaxf(mtB, __shfl_xor_sync(0xFFFFFFFFu, mtB, 1));
            mtB = fmaxf(mtB, __shfl_xor_sync(0xFFFFFFFFu, mtB, 2));

            float mnA = fmaxf(mrow[m][0], mtA);
            float mnB = fmaxf(mrow[m][1], mtB);
            float corrA = ex2((mrow[m][0] - mnA) * LS);
            float corrB = ex2((mrow[m][1] - mnB) * LS);
            mrow[m][0] = mnA; mrow[m][1] = mnB;
            const float bA = mnA * LS, bB = mnB * LS;

            uint32_t pa[4][4];
#pragma unroll
            for (int s = 0; s < 4; s++) {
                pa[s][0] = ex2_h2(h2pack(fmaf(S[2*s][0],   LS, -bA),
                                         fmaf(S[2*s][1],   LS, -bA)));
                pa[s][1] = ex2_h2(h2pack(fmaf(S[2*s][2],   LS, -bB),
                                         fmaf(S[2*s][3],   LS, -bB)));
                pa[s][2] = ex2_h2(h2pack(fmaf(S[2*s+1][0], LS, -bA),
                                         fmaf(S[2*s+1][1], LS, -bA)));
                pa[s][3] = ex2_h2(h2pack(fmaf(S[2*s+1][2], LS, -bB),
                                         fmaf(S[2*s+1][3], LS, -bB)));
            }

            // Rescale O/L(m)
            Lacc[m][0] *= corrA; Lacc[m][1] *= corrA;
            Lacc[m][2] *= corrB; Lacc[m][3] *= corrB;
#pragma unroll
            for (int n = 0; n < 8; n++) {
                Oacc[m][n][0] *= corrA; Oacc[m][n][1] *= corrA;
                Oacc[m][n][2] *= corrB; Oacc[m][n][3] *= corrB;
            }

            // L += P . ones
#pragma unroll
            for (int s = 0; s < 4; s++)
                mma_f16(Lacc[m], pa[s], ONES2, ONES2);

            // MMA2: O(m) += P . V with ping-pong prefetch.
            ldsm_x4_t(bb[0][0], bb[0][1], bb[0][2], bb[0][3], vbase);
#pragma unroll
            for (int i = 0; i < 16; i++) {
                const int c2 = i & 1;
                if (i < 15) {
                    const int ni = i + 1;
                    ldsm_x4_t(bb[c2 ^ 1][0], bb[c2 ^ 1][1],
                              bb[c2 ^ 1][2], bb[c2 ^ 1][3],
                              vbase + (ni >> 2) * (16 * RPITCH) + (ni & 3) * 32);
                }
                const int s = i >> 2, nd = i & 3;
                mma_f16(Oacc[m][2 * nd],     pa[s], bb[c2][0], bb[c2][1]);
                mma_f16(Oacc[m][2 * nd + 1], pa[s], bb[c2][2], bb[c2][3]);
            }
        }
    }

    // ---- Normalize, write fp16 to g_attnh ----
#pragma unroll
    for (int m = 0; m < 2; m++) {
        float invA = 1.f / Lacc[m][0];
        float invB = 1.f / Lacc[m][2];
        int rA = q0 + wq0 + 16 * m + g;
        int rB = rA + 8;
        __half* opA = g_attnh + ((size_t)(b * SEQ + rA)) * MODEL + h * HD;
        __half* opB = g_attnh + ((size_t)(b * SEQ + rB)) * MODEL + h * HD;
#pragma unroll
        for (int n = 0; n < 8; n++) {
            *(uint32_t*)(opA + n * 8 + 2 * t) =
                h2pack(Oacc[m][n][0] * invA, Oacc[m][n][1] * invA);
            *(uint32_t*)(opB + n * 8 + 2 * t) =
                h2pack(Oacc[m][n][2] * invB, Oacc[m][n][3] * invB);
        }
    }
}

// ---------------------------------------------------------------------------
// Output projection via mma.sync: out[8192,64] = Ah[8192,512]@Wh[512,64]+b.
// 128 CTAs x 64 rows, 128 threads (4 warps x 16 rows). Double-buffered
// cp.async staging of A[64,64] and W[64,64] fp16 chunks (8 k-chunks).
// ---------------------------------------------------------------------------
#define PAS_B 0                          // A: 64*144 x2
#define PWS_B (2 * 9216)                 // W: 64*144 x2
#define PSMEM (4 * 9216)                 // 36864 B
__global__ __launch_bounds__(128)
void proj_kernel(const float* __restrict__ bias, float* __restrict__ out)
{
    __shared__ __align__(16) char smc[PSMEM];
    const uint32_t sb = smem_u32(smc);

    const int tid  = threadIdx.x;
    const int lane = tid & 31;
    const int wid  = tid >> 5;
    const int g    = lane >> 2;
    const int t    = lane & 3;
    const int row0 = blockIdx.x * 64;

    const uint32_t aoff = (wid * 16 + (lane & 15)) * RPITCH + (lane >> 4) * 16;
    const uint32_t woff = ((lane & 7) + (((lane >> 3) & 1) << 3)) * RPITCH
                        + ((lane >> 4) & 1) * 16;

    float acc[8][4];
#pragma unroll
    for (int n = 0; n < 8; n++)
#pragma unroll
        for (int i = 0; i < 4; i++) acc[n][i] = 0.f;

    // Stage chunk 0
    {
#pragma unroll
        for (int r = 0; r < 4; r++) {
            int c = r * 128 + tid;            // 512 chunks each
            int row = c >> 3, c8 = c & 7;
            cp_async16(sb + PAS_B + row * RPITCH + c8 * 16,
                       g_attnh + (size_t)(row0 + row) * MODEL + c8 * 8);
            cp_async16(sb + PWS_B + row * RPITCH + c8 * 16,
                       g_wh + (size_t)row * HD + c8 * 8);
        }
        CP_COMMIT();
    }

    for (int kc = 0; kc < 8; kc++) {
        const int cur = kc & 1;
        __syncthreads();                      // all warps done with buf cur^1
        if (kc + 1 < 8) {
            const uint32_t ab = sb + PAS_B + (cur ^ 1) * 9216;
            const uint32_t wb = sb + PWS_B + (cur ^ 1) * 9216;
            const int k0 = (kc + 1) * 64;
#pragma unroll
            for (int r = 0; r < 4; r++) {
                int c = r * 128 + tid;
                int row = c >> 3, c8 = c & 7;
                cp_async16(ab + row * RPITCH + c8 * 16,
                           g_attnh + (size_t)(row0 + row) * MODEL + k0 + c8 * 8);
                cp_async16(wb + row * RPITCH + c8 * 16,
                           g_wh + (size_t)(k0 + row) * HD + c8 * 8);
            }
            CP_COMMIT();
            CP_WAIT(1);
        } else {
            CP_WAIT(0);
        }
        __syncthreads();                      // chunk kc visible

        const uint32_t abase = sb + PAS_B + cur * 9216 + aoff;
        const uint32_t wbase = sb + PWS_B + cur * 9216 + woff;
#pragma unroll
        for (int s = 0; s < 4; s++) {
            uint32_t a[4];
            ldsm_x4(a[0], a[1], a[2], a[3], abase + s * 32);
#pragma unroll
            for (int nd = 0; nd < 4; nd++) {
                uint32_t b0, b1, b2, b3;
                ldsm_x4_t(b0, b1, b2, b3, wbase + s * (16 * RPITCH) + nd * 32);
                mma_f16(acc[2 * nd],     a, b0, b1);
                mma_f16(acc[2 * nd + 1], a, b2, b3);
            }
        }
    }

    // Epilogue: add bias, write fp32
    int rA = row0 + wid * 16 + g;
    int rB = rA + 8;
#pragma unroll
    for (int n = 0; n < 8; n++) {
        int c = n * 8 + 2 * t;
        float b0 = bias[c], b1 = bias[c + 1];
        *(float2*)(out + (size_t)rA * HD + c) =
            make_float2(acc[n][0] + b0, acc[n][1] + b1);
        *(float2*)(out + (size_t)rB * HD + c) =
            make_float2(acc[n][2] + b0, acc[n][3] + b1);
    }
}

// ---------------------------------------------------------------------------
extern "C" void kernel_launch(void* const* d_in, const int* in_sizes, int n_in,
                              void* d_out, int out_size)
{
    const float* q    = (const float*)d_in[0];
    const float* k    = (const float*)d_in[1];
    const float* v    = (const float*)d_in[2];
    const float* Wout = (const float*)d_in[3];
    const float* bout = (const float*)d_in[4];
    float* out = (float*)d_out;

    static bool attr_set = false;
    if (!attr_set) {
        cudaFuncSetAttribute(attn_tc_kernel,
                             cudaFuncAttributeMaxDynamicSharedMemorySize, SMEM_BYTES);
        attr_set = true;
    }

    cvt_kernel<<<dim3(2048, 2), 256>>>(k, v);
    wcvt_kernel<<<16, 256>>>(Wout);

    // One spacer keeps attn_tc_kernel in the ncu capture slot (launch #6).
    noop_kernel<<<1, 1>>>();

    dim3 agrid(BATCH * NH, SEQ / BM);
    attn_tc_kernel<<<agrid, BM, SMEM_BYTES>>>(q);

    proj_kernel<<<(BATCH * SEQ) / 64, 128>>>(bout, out);
}